// round 11
// baseline (speedup 1.0000x reference)
#include <cuda_runtime.h>
#include <math.h>

#define T_  4
#define C_  512
#define H_  192
#define W_  192
#define HW_ (H_ * W_)
#define CHW_ ((size_t)C_ * HW_)
#define W4_ (W_ / 4)

struct TCoef { float ax, bx, cx, ay, by, cy; };
struct TInt  { int kx, ky; float fx, fy; };

__device__ float g_part[C_ * 4];
__device__ TCoef g_tc[T_];
__device__ TInt  g_ti[T_];
__device__ int   g_fast;

// ---------------------------------------------------------------------------
// Kernel 1: GAP, 4 partial blocks per channel (proven ~15us @ 61-66% DRAM)
// ---------------------------------------------------------------------------
__global__ void gap_kernel(const float* __restrict__ F) {
    int c = blockIdx.x >> 2;
    int q = blockIdx.x & 3;
    const int n4q = HW_ / 16;
    const float4* p = reinterpret_cast<const float4*>(F + (size_t)c * HW_) + q * n4q;
    float s = 0.f;
    #pragma unroll
    for (int i = 0; i < 9; ++i) {
        float4 v = p[i * 256 + threadIdx.x];
        s += (v.x + v.y) + (v.z + v.w);
    }
    #pragma unroll
    for (int o = 16; o > 0; o >>= 1) s += __shfl_xor_sync(0xffffffffu, s, o);
    __shared__ float sh[8];
    if ((threadIdx.x & 31) == 0) sh[threadIdx.x >> 5] = s;
    __syncthreads();
    if (threadIdx.x == 0) {
        float t = 0.f;
        #pragma unroll
        for (int i = 0; i < 8; ++i) t += sh[i];
        g_part[c * 4 + q] = t;
    }
}

// ---------------------------------------------------------------------------
// Kernel 2: theta
// ---------------------------------------------------------------------------
__global__ void theta_kernel(const float* __restrict__ w1,
                             const float* __restrict__ b1,
                             const float* __restrict__ a,
                             float* __restrict__ out_tail) {
    int warp = threadIdx.x >> 5;
    int lane = threadIdx.x & 31;

    float s = 0.f;
    for (int k = lane; k < C_; k += 32) {
        float4 pp = *reinterpret_cast<const float4*>(&g_part[4 * k]);
        s += ((pp.x + pp.y) + (pp.z + pp.w)) * w1[warp * C_ + k];
    }
    #pragma unroll
    for (int o = 16; o > 0; o >>= 1) s += __shfl_xor_sync(0xffffffffu, s, o);

    __shared__ float Bs[2 * T_];
    if (lane == 0) Bs[warp] = tanhf(s * (1.0f / (float)HW_) + b1[warp]);
    __syncthreads();

    float a00 = a[0], a01 = a[1], a10 = a[2], a11 = a[3];

    if (threadIdx.x == 0)
        g_fast = (a00 == 1.0f && a01 == 0.0f && a10 == 0.0f && a11 == 1.0f) ? 1 : 0;

    if (threadIdx.x < T_) {
        int t = threadIdx.x;
        float bx = Bs[2 * t + 0];
        float by = Bs[2 * t + 1];
        TCoef tc;
        tc.ax = a00;
        tc.bx = a01 * ((float)W_ / (float)H_);
        tc.cx = 0.5f * (a00 - a00 * (float)W_ + a01 * ((float)W_ / (float)H_)
                        - a01 * (float)W_ + bx * (float)W_ + (float)W_ - 1.0f);
        tc.ay = a10 * ((float)H_ / (float)W_);
        tc.by = a11;
        tc.cy = 0.5f * (a10 * ((float)H_ / (float)W_) - a10 * (float)H_ + a11
                        - a11 * (float)H_ + by * (float)H_ + (float)H_ - 1.0f);
        g_tc[t] = tc;

        TInt ti;
        float kxf = floorf(tc.cx), kyf = floorf(tc.cy);
        ti.kx = (int)kxf;  ti.fx = tc.cx - kxf;
        ti.ky = (int)kyf;  ti.fy = tc.cy - kyf;
        g_ti[t] = ti;
    }

    if (threadIdx.x < T_ * 4) out_tail[threadIdx.x] = a[threadIdx.x & 3];
    if (threadIdx.x < 2 * T_) out_tail[T_ * 4 + threadIdx.x] = Bs[threadIdx.x];
}

// ---------------------------------------------------------------------------
// Kernel 3: bilinear warp. ONE t per block (t = blockIdx.z): each scheduling
// wave writes a contiguous region of ONE t-plane (DRAM write locality), and
// each thread does only 4 loads + 1 store. Body identical to R10's per-t body.
// ---------------------------------------------------------------------------
__global__ void __launch_bounds__(384) sample_kernel(const float* __restrict__ F,
                                                     float* __restrict__ out) {
    int w4 = threadIdx.x;                    // 0..47
    int h  = blockIdx.x * 8 + threadIdx.y;   // 0..191
    int c  = blockIdx.y;                     // 0..511
    int t  = blockIdx.z;                     // 0..3
    int w0 = w4 * 4;

    const float* Fc = F + (size_t)c * HW_;
    float* outp = out + (size_t)t * CHW_ + (size_t)c * HW_ + (size_t)h * W_ + w0;

    if (g_fast) {
        TInt ti = g_ti[t];
        int y0 = h + ti.ky;
        bool vy0 = (unsigned)y0 < (unsigned)H_;
        bool vy1 = (unsigned)(y0 + 1) < (unsigned)H_;
        int x0 = w0 + ti.kx;
        int s  = ti.kx & 3;                 // uniform across grid
        int base4 = (x0 - s) >> 2;          // aligned float4 index
        int b0 = min(max(base4, 0), W4_ - 1);
        int b1 = min(max(base4 + 1, 0), W4_ - 1);

        const float4* r0p = reinterpret_cast<const float4*>(
            Fc + (size_t)(vy0 ? y0 : 0) * W_);
        const float4* r1p = reinterpret_cast<const float4*>(
            Fc + (size_t)(vy1 ? (y0 + 1) : 0) * W_);

        float4 A0 = __ldg(&r0p[b0]);
        float4 A1 = __ldg(&r0p[b1]);
        float4 B0 = __ldg(&r1p[b0]);
        float4 B1 = __ldg(&r1p[b1]);
        if (!vy0) { A0 = make_float4(0,0,0,0); A1 = make_float4(0,0,0,0); }
        if (!vy1) { B0 = make_float4(0,0,0,0); B1 = make_float4(0,0,0,0); }

        float fy = ti.fy;
        float m0 = A0.x + fy * (B0.x - A0.x);
        float m1 = A0.y + fy * (B0.y - A0.y);
        float m2 = A0.z + fy * (B0.z - A0.z);
        float m3 = A0.w + fy * (B0.w - A0.w);
        float m4 = A1.x + fy * (B1.x - A1.x);
        float m5 = A1.y + fy * (B1.y - A1.y);
        float m6 = A1.z + fy * (B1.z - A1.z);
        float m7 = A1.w + fy * (B1.w - A1.w);

        int xb = 4 * base4;
        if ((unsigned)(xb + 0) >= (unsigned)W_) m0 = 0.f;
        if ((unsigned)(xb + 1) >= (unsigned)W_) m1 = 0.f;
        if ((unsigned)(xb + 2) >= (unsigned)W_) m2 = 0.f;
        if ((unsigned)(xb + 3) >= (unsigned)W_) m3 = 0.f;
        if ((unsigned)(xb + 4) >= (unsigned)W_) m4 = 0.f;
        if ((unsigned)(xb + 5) >= (unsigned)W_) m5 = 0.f;
        if ((unsigned)(xb + 6) >= (unsigned)W_) m6 = 0.f;
        if ((unsigned)(xb + 7) >= (unsigned)W_) m7 = 0.f;

        float fx = ti.fx;
        float4 o;
        #define MIX_(e0, e1) ((e0) + fx * ((e1) - (e0)))
        switch (s) {   // uniform branch: all warps take the same case
            case 0: o.x=MIX_(m0,m1); o.y=MIX_(m1,m2); o.z=MIX_(m2,m3); o.w=MIX_(m3,m4); break;
            case 1: o.x=MIX_(m1,m2); o.y=MIX_(m2,m3); o.z=MIX_(m3,m4); o.w=MIX_(m4,m5); break;
            case 2: o.x=MIX_(m2,m3); o.y=MIX_(m3,m4); o.z=MIX_(m4,m5); o.w=MIX_(m5,m6); break;
            default:o.x=MIX_(m3,m4); o.y=MIX_(m4,m5); o.z=MIX_(m5,m6); o.w=MIX_(m6,m7); break;
        }
        #undef MIX_
        __stcs(reinterpret_cast<float4*>(outp), o);
    } else {
        // General affine fallback (scalar gathers) for this t
        TCoef tc = g_tc[t];
        float bases_x = tc.bx * (float)h + tc.cx;
        float bases_y = tc.by * (float)h + tc.cy;
        float4 o;
        float* op = reinterpret_cast<float*>(&o);
        #pragma unroll
        for (int j = 0; j < 4; ++j) {
            float wf = (float)(w0 + j);
            float ix = tc.ax * wf + bases_x;
            float iy = tc.ay * wf + bases_y;
            float ix0f = floorf(ix), iy0f = floorf(iy);
            float fx = ix - ix0f,   fy = iy - iy0f;
            int x0 = (int)ix0f, y0 = (int)iy0f;
            int x1 = x0 + 1,    y1 = y0 + 1;
            bool vx0 = (unsigned)x0 < (unsigned)W_;
            bool vx1 = (unsigned)x1 < (unsigned)W_;
            bool vy0 = (unsigned)y0 < (unsigned)H_;
            bool vy1 = (unsigned)y1 < (unsigned)H_;
            const float* r0 = Fc + (size_t)(vy0 ? y0 : 0) * W_;
            const float* r1 = Fc + (size_t)(vy1 ? y1 : 0) * W_;
            float v00 = (vy0 && vx0) ? __ldg(r0 + x0) : 0.f;
            float v01 = (vy0 && vx1) ? __ldg(r0 + x1) : 0.f;
            float v10 = (vy1 && vx0) ? __ldg(r1 + x0) : 0.f;
            float v11 = (vy1 && vx1) ? __ldg(r1 + x1) : 0.f;
            float wx0 = 1.f - fx, wx1 = fx;
            float wy0 = 1.f - fy, wy1 = fy;
            op[j] = wy0 * (wx0 * v00 + wx1 * v01) + wy1 * (wx0 * v10 + wx1 * v11);
        }
        __stcs(reinterpret_cast<float4*>(outp), o);
    }
}

// ---------------------------------------------------------------------------
extern "C" void kernel_launch(void* const* d_in, const int* in_sizes, int n_in,
                              void* d_out, int out_size) {
    const float* F  = (const float*)d_in[0];
    const float* w1 = (const float*)d_in[1];
    const float* b1 = (const float*)d_in[2];
    const float* a  = (const float*)d_in[3];
    float* out = (float*)d_out;

    float* out_tail = out + (size_t)T_ * CHW_;

    gap_kernel<<<C_ * 4, 256>>>(F);
    theta_kernel<<<1, 256>>>(w1, b1, a, out_tail);

    dim3 blk(48, 8);                  // 384 threads
    dim3 grd(H_ / 8, C_, T_);         // 24 x 512 x 4 blocks
    sample_kernel<<<grd, blk>>>(F, out);
}

// round 12
// speedup vs baseline: 1.1264x; 1.1264x over previous
#include <cuda_runtime.h>
#include <math.h>

#define T_  4
#define C_  512
#define H_  192
#define W_  192
#define HW_ (H_ * W_)
#define CHW_ ((size_t)C_ * HW_)
#define W4_ (W_ / 4)
#define NBLK_ 296            // 2 blocks per SM (148 SMs) -> guaranteed co-resident
#define NTASK_ (C_ * 4)      // 2048 quarter-channel GAP tasks
#define NTILE_ (C_ * (H_ / 8))  // 12288 sample tiles (channel x 8-row block)

struct TCoef { float ax, bx, cx, ay, by, cy; };
struct TInt  { int kx, ky; float fx, fy; };

__device__ float    g_part[C_ * 4];
__device__ unsigned g_in;    // barrier arrive counter (zero-init; self-resetting)
__device__ unsigned g_out;   // barrier depart counter

// ---------------------------------------------------------------------------
// Fused persistent kernel: GAP -> global barrier -> per-block theta -> sample
// ---------------------------------------------------------------------------
__global__ void __launch_bounds__(384) fused_kernel(
    const float* __restrict__ F,
    const float* __restrict__ w1,
    const float* __restrict__ b1,
    const float* __restrict__ a,
    float* __restrict__ out,
    float* __restrict__ out_tail) {

    const int tid  = threadIdx.y * 48 + threadIdx.x;   // 0..383
    const int lane = tid & 31;
    const int wid  = tid >> 5;                          // 0..11

    __shared__ float sred[12];
    __shared__ float Bs[2 * T_];
    __shared__ TCoef s_tc[T_];
    __shared__ TInt  s_ti[T_];
    __shared__ int   s_fast;

    // ================= Phase 1: GAP partial sums =================
    for (int task = blockIdx.x; task < NTASK_; task += NBLK_) {
        int c = task >> 2;
        int q = task & 3;
        const float4* p = reinterpret_cast<const float4*>(F + (size_t)c * HW_)
                          + q * (HW_ / 16);
        float s = 0.f;
        #pragma unroll
        for (int i = 0; i < 6; ++i) {               // 6 * 384 = 2304
            float4 v = p[i * 384 + tid];
            s += (v.x + v.y) + (v.z + v.w);
        }
        #pragma unroll
        for (int o = 16; o > 0; o >>= 1) s += __shfl_xor_sync(0xffffffffu, s, o);
        if (lane == 0) sred[wid] = s;
        __syncthreads();
        if (tid == 0) {
            float t = 0.f;
            #pragma unroll
            for (int i = 0; i < 12; ++i) t += sred[i];
            g_part[c * 4 + q] = t;
        }
        __syncthreads();
    }

    // ================= Global barrier (in/out, self-resetting) =================
    __threadfence();                // publish g_part
    if (tid == 0) {
        atomicAdd(&g_in, 1u);
        while (*(volatile unsigned*)&g_in < NBLK_) { }
        __threadfence();            // observe all g_part
        unsigned y = atomicAdd(&g_out, 1u);
        if (y == NBLK_ - 1) {       // last block out: reset for next graph replay
            g_in  = 0;
            g_out = 0;
        }
    }
    __syncthreads();

    // ================= Per-block theta (redundant, cheap) =================
    if (wid < 8) {   // 8 warps: warp i computes B_lin[i]
        float s = 0.f;
        for (int k = lane; k < C_; k += 32) {
            float4 pp = *reinterpret_cast<const float4*>(&g_part[4 * k]);
            s += ((pp.x + pp.y) + (pp.z + pp.w)) * w1[wid * C_ + k];
        }
        #pragma unroll
        for (int o = 16; o > 0; o >>= 1) s += __shfl_xor_sync(0xffffffffu, s, o);
        if (lane == 0) Bs[wid] = tanhf(s * (1.0f / (float)HW_) + b1[wid]);
    }
    __syncthreads();

    float a00 = a[0], a01 = a[1], a10 = a[2], a11 = a[3];

    if (tid < T_) {
        int t = tid;
        float bx = Bs[2 * t + 0];
        float by = Bs[2 * t + 1];
        TCoef tc;
        tc.ax = a00;
        tc.bx = a01 * ((float)W_ / (float)H_);
        tc.cx = 0.5f * (a00 - a00 * (float)W_ + a01 * ((float)W_ / (float)H_)
                        - a01 * (float)W_ + bx * (float)W_ + (float)W_ - 1.0f);
        tc.ay = a10 * ((float)H_ / (float)W_);
        tc.by = a11;
        tc.cy = 0.5f * (a10 * ((float)H_ / (float)W_) - a10 * (float)H_ + a11
                        - a11 * (float)H_ + by * (float)H_ + (float)H_ - 1.0f);
        s_tc[t] = tc;

        TInt ti;
        float kxf = floorf(tc.cx), kyf = floorf(tc.cy);
        ti.kx = (int)kxf;  ti.fx = tc.cx - kxf;
        ti.ky = (int)kyf;  ti.fy = tc.cy - kyf;
        s_ti[t] = ti;
    }
    if (tid == 0)
        s_fast = (a00 == 1.0f && a01 == 0.0f && a10 == 0.0f && a11 == 1.0f) ? 1 : 0;

    // Output tail written by block 0
    if (blockIdx.x == 0) {
        if (tid < T_ * 4) out_tail[tid] = a[tid & 3];
        if (tid < 2 * T_) out_tail[T_ * 4 + tid] = Bs[tid];
    }
    __syncthreads();

    const int fast = s_fast;
    const int w4 = threadIdx.x;          // 0..47
    const int w0 = w4 * 4;

    // ================= Phase 3: sample (R10 body, tile loop) =================
    for (int tile = blockIdx.x; tile < NTILE_; tile += NBLK_) {
        int c  = tile / (H_ / 8);
        int hb = tile - c * (H_ / 8);
        int h  = hb * 8 + threadIdx.y;

        const float* Fc = F + (size_t)c * HW_;
        float* outp = out + (size_t)c * HW_ + (size_t)h * W_ + w0;

        if (fast) {
            #pragma unroll
            for (int t = 0; t < T_; ++t) {
                TInt ti = s_ti[t];
                int y0 = h + ti.ky;
                bool vy0 = (unsigned)y0 < (unsigned)H_;
                bool vy1 = (unsigned)(y0 + 1) < (unsigned)H_;
                int x0 = w0 + ti.kx;
                int s  = ti.kx & 3;                 // uniform across grid
                int base4 = (x0 - s) >> 2;
                int b0 = min(max(base4, 0), W4_ - 1);
                int b1 = min(max(base4 + 1, 0), W4_ - 1);

                const float4* r0p = reinterpret_cast<const float4*>(
                    Fc + (size_t)(vy0 ? y0 : 0) * W_);
                const float4* r1p = reinterpret_cast<const float4*>(
                    Fc + (size_t)(vy1 ? (y0 + 1) : 0) * W_);

                float4 A0 = __ldg(&r0p[b0]);
                float4 A1 = __ldg(&r0p[b1]);
                float4 B0 = __ldg(&r1p[b0]);
                float4 B1 = __ldg(&r1p[b1]);
                if (!vy0) { A0 = make_float4(0,0,0,0); A1 = make_float4(0,0,0,0); }
                if (!vy1) { B0 = make_float4(0,0,0,0); B1 = make_float4(0,0,0,0); }

                float fy = ti.fy;
                float m0 = A0.x + fy * (B0.x - A0.x);
                float m1 = A0.y + fy * (B0.y - A0.y);
                float m2 = A0.z + fy * (B0.z - A0.z);
                float m3 = A0.w + fy * (B0.w - A0.w);
                float m4 = A1.x + fy * (B1.x - A1.x);
                float m5 = A1.y + fy * (B1.y - A1.y);
                float m6 = A1.z + fy * (B1.z - A1.z);
                float m7 = A1.w + fy * (B1.w - A1.w);

                int xb = 4 * base4;
                if ((unsigned)(xb + 0) >= (unsigned)W_) m0 = 0.f;
                if ((unsigned)(xb + 1) >= (unsigned)W_) m1 = 0.f;
                if ((unsigned)(xb + 2) >= (unsigned)W_) m2 = 0.f;
                if ((unsigned)(xb + 3) >= (unsigned)W_) m3 = 0.f;
                if ((unsigned)(xb + 4) >= (unsigned)W_) m4 = 0.f;
                if ((unsigned)(xb + 5) >= (unsigned)W_) m5 = 0.f;
                if ((unsigned)(xb + 6) >= (unsigned)W_) m6 = 0.f;
                if ((unsigned)(xb + 7) >= (unsigned)W_) m7 = 0.f;

                float fx = ti.fx;
                float4 o;
                #define MIX_(e0, e1) ((e0) + fx * ((e1) - (e0)))
                switch (s) {
                    case 0: o.x=MIX_(m0,m1); o.y=MIX_(m1,m2); o.z=MIX_(m2,m3); o.w=MIX_(m3,m4); break;
                    case 1: o.x=MIX_(m1,m2); o.y=MIX_(m2,m3); o.z=MIX_(m3,m4); o.w=MIX_(m4,m5); break;
                    case 2: o.x=MIX_(m2,m3); o.y=MIX_(m3,m4); o.z=MIX_(m4,m5); o.w=MIX_(m5,m6); break;
                    default:o.x=MIX_(m3,m4); o.y=MIX_(m4,m5); o.z=MIX_(m5,m6); o.w=MIX_(m6,m7); break;
                }
                #undef MIX_
                __stcs(reinterpret_cast<float4*>(outp + (size_t)t * CHW_), o);
            }
        } else {
            #pragma unroll
            for (int t = 0; t < T_; ++t) {
                TCoef tc = s_tc[t];
                float bases_x = tc.bx * (float)h + tc.cx;
                float bases_y = tc.by * (float)h + tc.cy;
                float4 o;
                float* op = reinterpret_cast<float*>(&o);
                #pragma unroll
                for (int j = 0; j < 4; ++j) {
                    float wf = (float)(w0 + j);
                    float ix = tc.ax * wf + bases_x;
                    float iy = tc.ay * wf + bases_y;
                    float ix0f = floorf(ix), iy0f = floorf(iy);
                    float fx = ix - ix0f,   fy = iy - iy0f;
                    int x0 = (int)ix0f, y0 = (int)iy0f;
                    int x1 = x0 + 1,    y1 = y0 + 1;
                    bool vx0 = (unsigned)x0 < (unsigned)W_;
                    bool vx1 = (unsigned)x1 < (unsigned)W_;
                    bool vy0 = (unsigned)y0 < (unsigned)H_;
                    bool vy1 = (unsigned)y1 < (unsigned)H_;
                    const float* r0 = Fc + (size_t)(vy0 ? y0 : 0) * W_;
                    const float* r1 = Fc + (size_t)(vy1 ? y1 : 0) * W_;
                    float v00 = (vy0 && vx0) ? __ldg(r0 + x0) : 0.f;
                    float v01 = (vy0 && vx1) ? __ldg(r0 + x1) : 0.f;
                    float v10 = (vy1 && vx0) ? __ldg(r1 + x0) : 0.f;
                    float v11 = (vy1 && vx1) ? __ldg(r1 + x1) : 0.f;
                    float wx0 = 1.f - fx, wx1 = fx;
                    float wy0 = 1.f - fy, wy1 = fy;
                    op[j] = wy0 * (wx0 * v00 + wx1 * v01) + wy1 * (wx0 * v10 + wx1 * v11);
                }
                __stcs(reinterpret_cast<float4*>(outp + (size_t)t * CHW_), o);
            }
        }
    }
}

// ---------------------------------------------------------------------------
extern "C" void kernel_launch(void* const* d_in, const int* in_sizes, int n_in,
                              void* d_out, int out_size) {
    const float* F  = (const float*)d_in[0];
    const float* w1 = (const float*)d_in[1];
    const float* b1 = (const float*)d_in[2];
    const float* a  = (const float*)d_in[3];
    float* out = (float*)d_out;

    float* out_tail = out + (size_t)T_ * CHW_;

    dim3 blk(48, 8);                 // 384 threads
    fused_kernel<<<NBLK_, blk>>>(F, w1, b1, a, out, out_tail);
}

// round 13
// speedup vs baseline: 1.2701x; 1.1275x over previous
#include <cuda_runtime.h>
#include <math.h>

#define T_  4
#define C_  512
#define H_  192
#define W_  192
#define HW_ (H_ * W_)
#define CHW_ ((size_t)C_ * HW_)
#define W4_ (W_ / 4)
#define NBLK_ 740            // 148 SMs x 5 blocks/SM -> one wave, all co-resident
#define NTASK_ (C_ * 4)      // 2048 quarter-channel GAP tasks
#define NTILE_ (C_ * (H_ / 8))  // 12288 sample tiles (channel x 8-row block)

struct TCoef { float ax, bx, cx, ay, by, cy; };
struct TInt  { int kx, ky; float fx, fy; };

__device__ float    g_part[C_ * 4];
__device__ unsigned g_in;    // barrier arrive counter (zero-init; self-resetting)
__device__ unsigned g_out;   // barrier depart counter

// ---------------------------------------------------------------------------
// Fused persistent kernel: GAP -> global barrier -> per-block theta -> sample
// 5 blocks/SM (94% occupancy) — R12 failed purely on 2/SM occupancy.
// ---------------------------------------------------------------------------
__global__ void __launch_bounds__(384, 5) fused_kernel(
    const float* __restrict__ F,
    const float* __restrict__ w1,
    const float* __restrict__ b1,
    const float* __restrict__ a,
    float* __restrict__ out,
    float* __restrict__ out_tail) {

    const int tid  = threadIdx.y * 48 + threadIdx.x;   // 0..383
    const int lane = tid & 31;
    const int wid  = tid >> 5;                          // 0..11

    __shared__ float sred[12];
    __shared__ float Bs[2 * T_];
    __shared__ TCoef s_tc[T_];
    __shared__ TInt  s_ti[T_];
    __shared__ int   s_fast;

    // ================= Phase 1: GAP partial sums =================
    for (int task = blockIdx.x; task < NTASK_; task += NBLK_) {
        int c = task >> 2;
        int q = task & 3;
        const float4* p = reinterpret_cast<const float4*>(F + (size_t)c * HW_)
                          + q * (HW_ / 16);
        float s = 0.f;
        #pragma unroll
        for (int i = 0; i < 6; ++i) {               // 6 * 384 = 2304
            float4 v = p[i * 384 + tid];
            s += (v.x + v.y) + (v.z + v.w);
        }
        #pragma unroll
        for (int o = 16; o > 0; o >>= 1) s += __shfl_xor_sync(0xffffffffu, s, o);
        if (lane == 0) sred[wid] = s;
        __syncthreads();
        if (tid == 0) {
            float t = 0.f;
            #pragma unroll
            for (int i = 0; i < 12; ++i) t += sred[i];
            g_part[c * 4 + q] = t;
        }
        __syncthreads();
    }

    // ================= Global barrier (in/out, self-resetting) =================
    __threadfence();                // publish g_part
    if (tid == 0) {
        atomicAdd(&g_in, 1u);
        while (*(volatile unsigned*)&g_in < NBLK_) { }
        __threadfence();            // observe all g_part
        unsigned y = atomicAdd(&g_out, 1u);
        if (y == NBLK_ - 1) {       // last block out: reset for next graph replay
            g_in  = 0;
            g_out = 0;
        }
    }
    __syncthreads();

    // ================= Per-block theta (redundant, cheap) =================
    if (wid < 8) {   // 8 warps: warp i computes B_lin[i]
        float s = 0.f;
        for (int k = lane; k < C_; k += 32) {
            float4 pp = *reinterpret_cast<const float4*>(&g_part[4 * k]);
            s += ((pp.x + pp.y) + (pp.z + pp.w)) * w1[wid * C_ + k];
        }
        #pragma unroll
        for (int o = 16; o > 0; o >>= 1) s += __shfl_xor_sync(0xffffffffu, s, o);
        if (lane == 0) Bs[wid] = tanhf(s * (1.0f / (float)HW_) + b1[wid]);
    }
    __syncthreads();

    float a00 = a[0], a01 = a[1], a10 = a[2], a11 = a[3];

    if (tid < T_) {
        int t = tid;
        float bx = Bs[2 * t + 0];
        float by = Bs[2 * t + 1];
        TCoef tc;
        tc.ax = a00;
        tc.bx = a01 * ((float)W_ / (float)H_);
        tc.cx = 0.5f * (a00 - a00 * (float)W_ + a01 * ((float)W_ / (float)H_)
                        - a01 * (float)W_ + bx * (float)W_ + (float)W_ - 1.0f);
        tc.ay = a10 * ((float)H_ / (float)W_);
        tc.by = a11;
        tc.cy = 0.5f * (a10 * ((float)H_ / (float)W_) - a10 * (float)H_ + a11
                        - a11 * (float)H_ + by * (float)H_ + (float)H_ - 1.0f);
        s_tc[t] = tc;

        TInt ti;
        float kxf = floorf(tc.cx), kyf = floorf(tc.cy);
        ti.kx = (int)kxf;  ti.fx = tc.cx - kxf;
        ti.ky = (int)kyf;  ti.fy = tc.cy - kyf;
        s_ti[t] = ti;
    }
    if (tid == 0)
        s_fast = (a00 == 1.0f && a01 == 0.0f && a10 == 0.0f && a11 == 1.0f) ? 1 : 0;

    // Output tail written by block 0
    if (blockIdx.x == 0) {
        if (tid < T_ * 4) out_tail[tid] = a[tid & 3];
        if (tid < 2 * T_) out_tail[T_ * 4 + tid] = Bs[tid];
    }
    __syncthreads();

    const int fast = s_fast;
    const int w4 = threadIdx.x;          // 0..47
    const int w0 = w4 * 4;

    // ================= Phase 3: sample (R10 body, tile loop) =================
    for (int tile = blockIdx.x; tile < NTILE_; tile += NBLK_) {
        int c  = tile / (H_ / 8);
        int hb = tile - c * (H_ / 8);
        int h  = hb * 8 + threadIdx.y;

        const float* Fc = F + (size_t)c * HW_;
        float* outp = out + (size_t)c * HW_ + (size_t)h * W_ + w0;

        if (fast) {
            #pragma unroll
            for (int t = 0; t < T_; ++t) {
                TInt ti = s_ti[t];
                int y0 = h + ti.ky;
                bool vy0 = (unsigned)y0 < (unsigned)H_;
                bool vy1 = (unsigned)(y0 + 1) < (unsigned)H_;
                int x0 = w0 + ti.kx;
                int s  = ti.kx & 3;                 // uniform across grid
                int base4 = (x0 - s) >> 2;
                int b0 = min(max(base4, 0), W4_ - 1);
                int b1 = min(max(base4 + 1, 0), W4_ - 1);

                const float4* r0p = reinterpret_cast<const float4*>(
                    Fc + (size_t)(vy0 ? y0 : 0) * W_);
                const float4* r1p = reinterpret_cast<const float4*>(
                    Fc + (size_t)(vy1 ? (y0 + 1) : 0) * W_);

                float4 A0 = __ldg(&r0p[b0]);
                float4 A1 = __ldg(&r0p[b1]);
                float4 B0 = __ldg(&r1p[b0]);
                float4 B1 = __ldg(&r1p[b1]);
                if (!vy0) { A0 = make_float4(0,0,0,0); A1 = make_float4(0,0,0,0); }
                if (!vy1) { B0 = make_float4(0,0,0,0); B1 = make_float4(0,0,0,0); }

                float fy = ti.fy;
                float m0 = A0.x + fy * (B0.x - A0.x);
                float m1 = A0.y + fy * (B0.y - A0.y);
                float m2 = A0.z + fy * (B0.z - A0.z);
                float m3 = A0.w + fy * (B0.w - A0.w);
                float m4 = A1.x + fy * (B1.x - A1.x);
                float m5 = A1.y + fy * (B1.y - A1.y);
                float m6 = A1.z + fy * (B1.z - A1.z);
                float m7 = A1.w + fy * (B1.w - A1.w);

                int xb = 4 * base4;
                if ((unsigned)(xb + 0) >= (unsigned)W_) m0 = 0.f;
                if ((unsigned)(xb + 1) >= (unsigned)W_) m1 = 0.f;
                if ((unsigned)(xb + 2) >= (unsigned)W_) m2 = 0.f;
                if ((unsigned)(xb + 3) >= (unsigned)W_) m3 = 0.f;
                if ((unsigned)(xb + 4) >= (unsigned)W_) m4 = 0.f;
                if ((unsigned)(xb + 5) >= (unsigned)W_) m5 = 0.f;
                if ((unsigned)(xb + 6) >= (unsigned)W_) m6 = 0.f;
                if ((unsigned)(xb + 7) >= (unsigned)W_) m7 = 0.f;

                float fx = ti.fx;
                float4 o;
                #define MIX_(e0, e1) ((e0) + fx * ((e1) - (e0)))
                switch (s) {
                    case 0: o.x=MIX_(m0,m1); o.y=MIX_(m1,m2); o.z=MIX_(m2,m3); o.w=MIX_(m3,m4); break;
                    case 1: o.x=MIX_(m1,m2); o.y=MIX_(m2,m3); o.z=MIX_(m3,m4); o.w=MIX_(m4,m5); break;
                    case 2: o.x=MIX_(m2,m3); o.y=MIX_(m3,m4); o.z=MIX_(m4,m5); o.w=MIX_(m5,m6); break;
                    default:o.x=MIX_(m3,m4); o.y=MIX_(m4,m5); o.z=MIX_(m5,m6); o.w=MIX_(m6,m7); break;
                }
                #undef MIX_
                __stcs(reinterpret_cast<float4*>(outp + (size_t)t * CHW_), o);
            }
        } else {
            #pragma unroll
            for (int t = 0; t < T_; ++t) {
                TCoef tc = s_tc[t];
                float bases_x = tc.bx * (float)h + tc.cx;
                float bases_y = tc.by * (float)h + tc.cy;
                float4 o;
                float* op = reinterpret_cast<float*>(&o);
                #pragma unroll
                for (int j = 0; j < 4; ++j) {
                    float wf = (float)(w0 + j);
                    float ix = tc.ax * wf + bases_x;
                    float iy = tc.ay * wf + bases_y;
                    float ix0f = floorf(ix), iy0f = floorf(iy);
                    float fx = ix - ix0f,   fy = iy - iy0f;
                    int x0 = (int)ix0f, y0 = (int)iy0f;
                    int x1 = x0 + 1,    y1 = y0 + 1;
                    bool vx0 = (unsigned)x0 < (unsigned)W_;
                    bool vx1 = (unsigned)x1 < (unsigned)W_;
                    bool vy0 = (unsigned)y0 < (unsigned)H_;
                    bool vy1 = (unsigned)y1 < (unsigned)H_;
                    const float* r0 = Fc + (size_t)(vy0 ? y0 : 0) * W_;
                    const float* r1 = Fc + (size_t)(vy1 ? y1 : 0) * W_;
                    float v00 = (vy0 && vx0) ? __ldg(r0 + x0) : 0.f;
                    float v01 = (vy0 && vx1) ? __ldg(r0 + x1) : 0.f;
                    float v10 = (vy1 && vx0) ? __ldg(r1 + x0) : 0.f;
                    float v11 = (vy1 && vx1) ? __ldg(r1 + x1) : 0.f;
                    float wx0 = 1.f - fx, wx1 = fx;
                    float wy0 = 1.f - fy, wy1 = fy;
                    op[j] = wy0 * (wx0 * v00 + wx1 * v01) + wy1 * (wx0 * v10 + wx1 * v11);
                }
                __stcs(reinterpret_cast<float4*>(outp + (size_t)t * CHW_), o);
            }
        }
    }
}

// ---------------------------------------------------------------------------
extern "C" void kernel_launch(void* const* d_in, const int* in_sizes, int n_in,
                              void* d_out, int out_size) {
    const float* F  = (const float*)d_in[0];
    const float* w1 = (const float*)d_in[1];
    const float* b1 = (const float*)d_in[2];
    const float* a  = (const float*)d_in[3];
    float* out = (float*)d_out;

    float* out_tail = out + (size_t)T_ * CHW_;

    dim3 blk(48, 8);                 // 384 threads
    fused_kernel<<<NBLK_, blk>>>(F, w1, b1, a, out, out_tail);
}

// round 14
// speedup vs baseline: 1.3137x; 1.0343x over previous
#include <cuda_runtime.h>
#include <math.h>

#define T_  4
#define C_  512
#define H_  192
#define W_  192
#define HW_ (H_ * W_)
#define CHW_ ((size_t)C_ * HW_)
#define W4_ (W_ / 4)

struct TCoef { float ax, bx, cx, ay, by, cy; };
struct TInt  { int k4, ky, s; float fx, fy; };

__device__ float  g_part[C_ * 4];
__device__ TCoef  g_tc[T_];
__device__ TInt   g_ti[T_];
__device__ int    g_fast;
__device__ float4 g_zero4;     // statically zero; never written — OOB load target

// ---------------------------------------------------------------------------
// Kernel 1: GAP, 4 partial blocks per channel (proven ~15us @ 61-66% DRAM)
// ---------------------------------------------------------------------------
__global__ void gap_kernel(const float* __restrict__ F) {
    int c = blockIdx.x >> 2;
    int q = blockIdx.x & 3;
    const int n4q = HW_ / 16;
    const float4* p = reinterpret_cast<const float4*>(F + (size_t)c * HW_) + q * n4q;
    float s = 0.f;
    #pragma unroll
    for (int i = 0; i < 9; ++i) {
        float4 v = p[i * 256 + threadIdx.x];
        s += (v.x + v.y) + (v.z + v.w);
    }
    #pragma unroll
    for (int o = 16; o > 0; o >>= 1) s += __shfl_xor_sync(0xffffffffu, s, o);
    __shared__ float sh[8];
    if ((threadIdx.x & 31) == 0) sh[threadIdx.x >> 5] = s;
    __syncthreads();
    if (threadIdx.x == 0) {
        float t = 0.f;
        #pragma unroll
        for (int i = 0; i < 8; ++i) t += sh[i];
        g_part[c * 4 + q] = t;
    }
}

// ---------------------------------------------------------------------------
// Kernel 2: theta
// ---------------------------------------------------------------------------
__global__ void theta_kernel(const float* __restrict__ w1,
                             const float* __restrict__ b1,
                             const float* __restrict__ a,
                             float* __restrict__ out_tail) {
    int warp = threadIdx.x >> 5;
    int lane = threadIdx.x & 31;

    float s = 0.f;
    for (int k = lane; k < C_; k += 32) {
        float4 pp = *reinterpret_cast<const float4*>(&g_part[4 * k]);
        s += ((pp.x + pp.y) + (pp.z + pp.w)) * w1[warp * C_ + k];
    }
    #pragma unroll
    for (int o = 16; o > 0; o >>= 1) s += __shfl_xor_sync(0xffffffffu, s, o);

    __shared__ float Bs[2 * T_];
    if (lane == 0) Bs[warp] = tanhf(s * (1.0f / (float)HW_) + b1[warp]);
    __syncthreads();

    float a00 = a[0], a01 = a[1], a10 = a[2], a11 = a[3];

    if (threadIdx.x == 0)
        g_fast = (a00 == 1.0f && a01 == 0.0f && a10 == 0.0f && a11 == 1.0f) ? 1 : 0;

    if (threadIdx.x < T_) {
        int t = threadIdx.x;
        float bx = Bs[2 * t + 0];
        float by = Bs[2 * t + 1];
        TCoef tc;
        tc.ax = a00;
        tc.bx = a01 * ((float)W_ / (float)H_);
        tc.cx = 0.5f * (a00 - a00 * (float)W_ + a01 * ((float)W_ / (float)H_)
                        - a01 * (float)W_ + bx * (float)W_ + (float)W_ - 1.0f);
        tc.ay = a10 * ((float)H_ / (float)W_);
        tc.by = a11;
        tc.cy = 0.5f * (a10 * ((float)H_ / (float)W_) - a10 * (float)H_ + a11
                        - a11 * (float)H_ + by * (float)H_ + (float)H_ - 1.0f);
        g_tc[t] = tc;

        TInt ti;
        float kxf = floorf(tc.cx), kyf = floorf(tc.cy);
        int kx = (int)kxf;
        ti.ky = (int)kyf;
        ti.fx = tc.cx - kxf;
        ti.fy = tc.cy - kyf;
        ti.s  = kx & 3;
        ti.k4 = kx >> 2;          // floor(kx/4), exact for negatives
        g_ti[t] = ti;
    }

    if (threadIdx.x < T_ * 4) out_tail[threadIdx.x] = a[threadIdx.x & 3];
    if (threadIdx.x < 2 * T_) out_tail[T_ * 4 + threadIdx.x] = Bs[threadIdx.x];
}

// ---------------------------------------------------------------------------
// Kernel 3: bilinear warp (R10 shape). OOB handled by redirecting the load
// POINTER to a zero float4 — removes all clamps, per-column masks, and
// y-zero selects from the hot path (uniform predication, no divergence).
// ---------------------------------------------------------------------------
__global__ void __launch_bounds__(384) sample_kernel(const float* __restrict__ F,
                                                     float* __restrict__ out) {
    int w4 = threadIdx.x;                    // 0..47
    int h  = blockIdx.x * 8 + threadIdx.y;   // 0..191
    int c  = blockIdx.y;                     // 0..511
    int w0 = w4 * 4;

    const float* Fc = F + (size_t)c * HW_;
    float* outp = out + (size_t)c * HW_ + (size_t)h * W_ + w0;
    const float4* zp = &g_zero4;

    if (g_fast) {
        #pragma unroll
        for (int t = 0; t < T_; ++t) {
            TInt ti = g_ti[t];
            int y0 = h + ti.ky;
            int base4 = w4 + ti.k4;
            bool vy0 = (unsigned)y0       < (unsigned)H_;
            bool vy1 = (unsigned)(y0 + 1) < (unsigned)H_;
            bool k0  = (unsigned)base4       < (unsigned)W4_;
            bool k1  = (unsigned)(base4 + 1) < (unsigned)W4_;

            const float4* r0 = reinterpret_cast<const float4*>(Fc) + y0 * W4_;
            const float4* r1 = r0 + W4_;

            const float4* q00 = (vy0 && k0) ? r0 + base4     : zp;
            const float4* q01 = (vy0 && k1) ? r0 + base4 + 1 : zp;
            const float4* q10 = (vy1 && k0) ? r1 + base4     : zp;
            const float4* q11 = (vy1 && k1) ? r1 + base4 + 1 : zp;

            float4 A0 = __ldg(q00);
            float4 A1 = __ldg(q01);
            float4 B0 = __ldg(q10);
            float4 B1 = __ldg(q11);

            float fy = ti.fy;
            float m0 = A0.x + fy * (B0.x - A0.x);
            float m1 = A0.y + fy * (B0.y - A0.y);
            float m2 = A0.z + fy * (B0.z - A0.z);
            float m3 = A0.w + fy * (B0.w - A0.w);
            float m4 = A1.x + fy * (B1.x - A1.x);
            float m5 = A1.y + fy * (B1.y - A1.y);
            float m6 = A1.z + fy * (B1.z - A1.z);
            float m7 = A1.w + fy * (B1.w - A1.w);

            float fx = ti.fx;
            float4 o;
            #define MIX_(e0, e1) ((e0) + fx * ((e1) - (e0)))
            switch (ti.s) {   // uniform branch: all warps take the same case
                case 0: o.x=MIX_(m0,m1); o.y=MIX_(m1,m2); o.z=MIX_(m2,m3); o.w=MIX_(m3,m4); break;
                case 1: o.x=MIX_(m1,m2); o.y=MIX_(m2,m3); o.z=MIX_(m3,m4); o.w=MIX_(m4,m5); break;
                case 2: o.x=MIX_(m2,m3); o.y=MIX_(m3,m4); o.z=MIX_(m4,m5); o.w=MIX_(m5,m6); break;
                default:o.x=MIX_(m3,m4); o.y=MIX_(m4,m5); o.z=MIX_(m5,m6); o.w=MIX_(m6,m7); break;
            }
            #undef MIX_
            __stcs(reinterpret_cast<float4*>(outp + (size_t)t * CHW_), o);
        }
    } else {
        // General affine fallback (scalar gathers)
        #pragma unroll
        for (int t = 0; t < T_; ++t) {
            TCoef tc = g_tc[t];
            float bases_x = tc.bx * (float)h + tc.cx;
            float bases_y = tc.by * (float)h + tc.cy;
            float4 o;
            float* op = reinterpret_cast<float*>(&o);
            #pragma unroll
            for (int j = 0; j < 4; ++j) {
                float wf = (float)(w0 + j);
                float ix = tc.ax * wf + bases_x;
                float iy = tc.ay * wf + bases_y;
                float ix0f = floorf(ix), iy0f = floorf(iy);
                float fx = ix - ix0f,   fy = iy - iy0f;
                int x0 = (int)ix0f, y0 = (int)iy0f;
                int x1 = x0 + 1,    y1 = y0 + 1;
                bool vx0 = (unsigned)x0 < (unsigned)W_;
                bool vx1 = (unsigned)x1 < (unsigned)W_;
                bool vy0 = (unsigned)y0 < (unsigned)H_;
                bool vy1 = (unsigned)y1 < (unsigned)H_;
                const float* r0 = Fc + (size_t)(vy0 ? y0 : 0) * W_;
                const float* r1 = Fc + (size_t)(vy1 ? y1 : 0) * W_;
                float v00 = (vy0 && vx0) ? __ldg(r0 + x0) : 0.f;
                float v01 = (vy0 && vx1) ? __ldg(r0 + x1) : 0.f;
                float v10 = (vy1 && vx0) ? __ldg(r1 + x0) : 0.f;
                float v11 = (vy1 && vx1) ? __ldg(r1 + x1) : 0.f;
                float wx0 = 1.f - fx, wx1 = fx;
                float wy0 = 1.f - fy, wy1 = fy;
                op[j] = wy0 * (wx0 * v00 + wx1 * v01) + wy1 * (wx0 * v10 + wx1 * v11);
            }
            __stcs(reinterpret_cast<float4*>(outp + (size_t)t * CHW_), o);
        }
    }
}

// ---------------------------------------------------------------------------
extern "C" void kernel_launch(void* const* d_in, const int* in_sizes, int n_in,
                              void* d_out, int out_size) {
    const float* F  = (const float*)d_in[0];
    const float* w1 = (const float*)d_in[1];
    const float* b1 = (const float*)d_in[2];
    const float* a  = (const float*)d_in[3];
    float* out = (float*)d_out;

    float* out_tail = out + (size_t)T_ * CHW_;

    gap_kernel<<<C_ * 4, 256>>>(F);
    theta_kernel<<<1, 256>>>(w1, b1, a, out_tail);

    dim3 blk(48, 8);              // 384 threads: w4 x 8 rows
    dim3 grd(H_ / 8, C_);         // 24 x 512 blocks
    sample_kernel<<<grd, blk>>>(F, out);
}